// round 5
// baseline (speedup 1.0000x reference)
#include <cuda_runtime.h>
#include <math.h>

// Fixed geometry: D=128, H=8, PAGE_SIZE=16, STREAMING_BUDGET=4096, NUM_SINK=4.
#define DD      128
#define HH      8
#define PAGE    16
#define BUDGET  4096
#define SINK    4
#define VEC_PER_ROW (DD/4)            // 32 float4 per head-row
#define F4_PER_PAGE (2*PAGE*HH*DD/4)  // 8192 float4 per page (k half then v half)

// log2(10000)/64, double precision
#define LOG2_1E4_OVER_64 0.20762050593045952

// Source head-row pointer for the streaming-gather (kv = 0 keys / 1 values).
__device__ __forceinline__ const float4*
resolve_row(const float4* __restrict__ cache, const float4* __restrict__ fresh,
            int b, int p, int kv, int ctx, int ql, int maxkv, int seq_len)
{
    bool active  = (ql > 0);
    bool rolling = active && (ctx + ql >  BUDGET);
    bool plain   = active && (ctx + ql <= BUDGET);

    if (rolling && p >= SINK && p < BUDGET - ql) {
        int srs = min(ctx, BUDGET) - (BUDGET - ql - SINK);
        int pos = min(max(p + srs - SINK, 0), maxkv - 1);
        int gp  = b * maxkv + pos;
        return cache + (size_t)(gp >> 4) * F4_PER_PAGE
                     + (size_t)(kv * PAGE + (gp & 15)) * (HH * VEC_PER_ROW);
    }
    if ((rolling && p >= BUDGET - ql && p < BUDGET) ||
        (plain   && p >= ctx         && p < ctx + ql)) {
        int sp = rolling ? (p - (BUDGET - ql)) : (p - ctx);
        sp = min(max(sp, 0), seq_len - 1);
        return fresh + ((size_t)(b * seq_len + sp) * HH) * VEC_PER_ROW;
    }
    int gp = b * maxkv + p;
    return cache + (size_t)(gp >> 4) * F4_PER_PAGE
                 + (size_t)(kv * PAGE + (gp & 15)) * (HH * VEC_PER_ROW);
}

// Destination float4 base of head-row (b,p,kv) in the paged output.
__device__ __forceinline__ size_t out_row_base(int b, int p, int kv, int maxkv)
{
    int gp = b * maxkv + p;
    return (size_t)(gp >> 4) * F4_PER_PAGE
         + (size_t)(kv * PAGE + (gp & 15)) * (HH * VEC_PER_ROW);
}

// Fused single-launch kernel. Flat grid over three regions:
//   [0, nA)        rope'd keys, p<BUDGET. thread = float4 pair (d4, d4+16).
//   [nA, nAV)      value gather, p<BUDGET. thread = 2 consecutive float4.
//   [nAV, ntot)    identity copy, p>=BUDGET (masks all false). 4 float4/thread.
__global__ __launch_bounds__(256)
void skv_fused(const float4* __restrict__ cache,
               const float4* __restrict__ knew,
               const float4* __restrict__ vnew,
               const int*    __restrict__ qlens,
               const int*    __restrict__ ctxp,
               float4*       __restrict__ out,
               int maxkv, int seq_len,
               int nA, int nAV,
               int id_shift, int id_mask, int ntot)
{
    __shared__ float sfreq[DD/2];
    int tid = threadIdx.x;
    int gid = blockIdx.x * 256 + tid;
    int blk0 = blockIdx.x * 256;

    // Blocks overlapping the rope region build the inv_freq table in smem
    // (double exp2 -> correctly-rounded fp32, same values as a double pow).
    if (blk0 < nA) {
        if (tid < DD/2)
            sfreq[tid] = (float)exp2(-(double)tid * LOG2_1E4_OVER_64);
        __syncthreads();
    }

    if (gid >= ntot) return;

    if (gid < nA) {
        // ---- RoPE keys ----
        int d4 = gid & 15;                 // lower-half float4 index (0..15)
        int h  = (gid >> 4) & (HH - 1);
        int p  = (gid >> 7) & (BUDGET - 1);
        int b  = gid >> 19;

        int ctx = *ctxp;
        int ql  = __ldg(&qlens[b]);

        const float4* row = resolve_row(cache, knew, b, p, 0, ctx, ql, maxkv, seq_len)
                            + h * VEC_PER_ROW;
        float4 x1 = __ldcs(&row[d4]);
        float4 x2 = __ldcs(&row[d4 + 16]);

        float fp = (float)p;
        int i0 = d4 * 4;
        float4 lo, hi;
        const float* a  = (const float*)&x1;
        const float* bb = (const float*)&x2;
        float* lf = (float*)&lo;
        float* hf = (float*)&hi;
        #pragma unroll
        for (int j = 0; j < 4; j++) {
            float s, c;
            sincosf(fp * sfreq[i0 + j], &s, &c);
            lf[j] = a[j] * c - bb[j] * s;
            hf[j] = a[j] * s + bb[j] * c;
        }

        float4* orow = out + out_row_base(b, p, 0, maxkv) + h * VEC_PER_ROW;
        __stcs(&orow[d4],      lo);
        __stcs(&orow[d4 + 16], hi);
    } else if (gid < nAV) {
        // ---- value gather, p < BUDGET ----
        int j  = gid - nA;
        int d4 = (j & 15) * 2;             // pair of consecutive float4
        int h  = (j >> 4) & (HH - 1);
        int p  = (j >> 7) & (BUDGET - 1);
        int b  = j >> 19;

        int ctx = *ctxp;
        int ql  = __ldg(&qlens[b]);
        const float4* row = resolve_row(cache, vnew, b, p, 1, ctx, ql, maxkv, seq_len)
                            + h * VEC_PER_ROW;
        float4 v0 = __ldcs(&row[d4]);
        float4 v1 = __ldcs(&row[d4 + 1]);
        float4* orow = out + out_row_base(b, p, 1, maxkv) + h * VEC_PER_ROW;
        __stcs(&orow[d4],     v0);
        __stcs(&orow[d4 + 1], v1);
    } else {
        // ---- identity region: per batch, pages [BUDGET/16, maxkv/16) ----
        // 4 float4 (64B) per thread, batched loads for MLP 4.
        int j = gid - nAV;
        int b = j >> id_shift;
        long long off = (long long)(j & id_mask);   // 4-float4 group in chunk
        long long base = ((long long)b * (maxkv / PAGE) + (BUDGET / PAGE))
                         * F4_PER_PAGE;
        long long idx = base + off * 4;
        float4 v0 = __ldcs(&cache[idx]);
        float4 v1 = __ldcs(&cache[idx + 1]);
        float4 v2 = __ldcs(&cache[idx + 2]);
        float4 v3 = __ldcs(&cache[idx + 3]);
        __stcs(&out[idx],     v0);
        __stcs(&out[idx + 1], v1);
        __stcs(&out[idx + 2], v2);
        __stcs(&out[idx + 3], v3);
    }
}

extern "C" void kernel_launch(void* const* d_in, const int* in_sizes, int n_in,
                              void* d_out, int out_size) {
    const float4* cache = (const float4*)d_in[0];
    const float4* knew  = (const float4*)d_in[1];
    const float4* vnew  = (const float4*)d_in[2];
    const int*    qlens = (const int*)d_in[3];
    const int*    ctxp  = (const int*)d_in[5];   // context_len scalar (device)

    int bsz = in_sizes[3];
    int total_pos = in_sizes[0] / (2 * HH * DD);
    int maxkv = total_pos / bsz;                 // 8192
    int seq_len = in_sizes[1] / (bsz * HH * DD); // 2048

    // Region sizes (threads)
    int nA  = bsz * BUDGET * HH * (VEC_PER_ROW / 2);   // rope pairs
    int nV  = bsz * BUDGET * HH * (VEC_PER_ROW / 2);   // value 32B units
    int nAV = nA + nV;

    int id_pages = maxkv / PAGE - BUDGET / PAGE;                  // per batch
    long long id_groups = (long long)id_pages * F4_PER_PAGE / 4;  // per batch (pow2)
    int id_shift = 0;
    while ((1LL << id_shift) < id_groups) id_shift++;
    int id_mask = (int)(id_groups - 1);

    int ntot = nAV + (int)(id_groups * bsz);
    int blocks = (ntot + 255) / 256;

    skv_fused<<<blocks, 256>>>(cache, knew, vnew, qlens, ctxp,
                               (float4*)d_out, maxkv, seq_len,
                               nA, nAV, id_shift, id_mask, ntot);
}

// round 6
// speedup vs baseline: 1.0316x; 1.0316x over previous
#include <cuda_runtime.h>
#include <math.h>

// Fixed geometry: D=128, H=8, PAGE_SIZE=16, STREAMING_BUDGET=4096, NUM_SINK=4.
#define DD      128
#define HH      8
#define PAGE    16
#define BUDGET  4096
#define SINK    4
#define VEC_PER_ROW (DD/4)            // 32 float4 per head-row
#define F4_PER_PAGE (2*PAGE*HH*DD/4)  // 8192 float4 per page (k half then v half)

// log2(10000)/64, double precision
#define LOG2_1E4_OVER_64 0.20762050593045952

// Source head-row pointer for the streaming-gather (kv = 0 keys / 1 values).
__device__ __forceinline__ const float4*
resolve_row(const float4* __restrict__ cache, const float4* __restrict__ fresh,
            int b, int p, int kv, int ctx, int ql, int maxkv, int seq_len)
{
    bool active  = (ql > 0);
    bool rolling = active && (ctx + ql >  BUDGET);
    bool plain   = active && (ctx + ql <= BUDGET);

    if (rolling && p >= SINK && p < BUDGET - ql) {
        int srs = min(ctx, BUDGET) - (BUDGET - ql - SINK);
        int pos = min(max(p + srs - SINK, 0), maxkv - 1);
        int gp  = b * maxkv + pos;
        return cache + (size_t)(gp >> 4) * F4_PER_PAGE
                     + (size_t)(kv * PAGE + (gp & 15)) * (HH * VEC_PER_ROW);
    }
    if ((rolling && p >= BUDGET - ql && p < BUDGET) ||
        (plain   && p >= ctx         && p < ctx + ql)) {
        int sp = rolling ? (p - (BUDGET - ql)) : (p - ctx);
        sp = min(max(sp, 0), seq_len - 1);
        return fresh + ((size_t)(b * seq_len + sp) * HH) * VEC_PER_ROW;
    }
    int gp = b * maxkv + p;
    return cache + (size_t)(gp >> 4) * F4_PER_PAGE
                 + (size_t)(kv * PAGE + (gp & 15)) * (HH * VEC_PER_ROW);
}

// Destination float4 base of head-row (b,p,kv) in the paged output.
__device__ __forceinline__ size_t out_row_base(int b, int p, int kv, int maxkv)
{
    int gp = b * maxkv + p;
    return (size_t)(gp >> 4) * F4_PER_PAGE
         + (size_t)(kv * PAGE + (gp & 15)) * (HH * VEC_PER_ROW);
}

// Fused single-launch kernel. Flat grid over three regions:
//   [0, nA)        rope'd keys, p<BUDGET. thread = float4 pair (d4, d4+16).
//   [nA, nAV)      value gather, p<BUDGET. thread = 2 consecutive float4.
//   [nAV, ntot)    identity copy, p>=BUDGET (masks all false). 2 float4/thread.
__global__ __launch_bounds__(256)
void skv_fused(const float4* __restrict__ cache,
               const float4* __restrict__ knew,
               const float4* __restrict__ vnew,
               const int*    __restrict__ qlens,
               const int*    __restrict__ ctxp,
               float4*       __restrict__ out,
               int maxkv, int seq_len,
               int nA, int nAV,
               int id_shift, int id_mask, int ntot)
{
    __shared__ float sfreq[DD/2];
    int tid = threadIdx.x;
    int gid = blockIdx.x * 256 + tid;
    int blk0 = blockIdx.x * 256;

    // Blocks overlapping the rope region build the inv_freq table in smem
    // (double exp2 -> correctly-rounded fp32, same values as a double pow).
    if (blk0 < nA) {
        if (tid < DD/2)
            sfreq[tid] = (float)exp2(-(double)tid * LOG2_1E4_OVER_64);
        __syncthreads();
    }

    if (gid >= ntot) return;

    if (gid < nA) {
        // ---- RoPE keys ----
        int d4 = gid & 15;                 // lower-half float4 index (0..15)
        int h  = (gid >> 4) & (HH - 1);
        int p  = (gid >> 7) & (BUDGET - 1);
        int b  = gid >> 19;

        int ctx = *ctxp;
        int ql  = __ldg(&qlens[b]);

        const float4* row = resolve_row(cache, knew, b, p, 0, ctx, ql, maxkv, seq_len)
                            + h * VEC_PER_ROW;
        float4 x1 = __ldg(&row[d4]);
        float4 x2 = __ldg(&row[d4 + 16]);

        float fp = (float)p;
        int i0 = d4 * 4;
        float4 lo, hi;
        const float* a  = (const float*)&x1;
        const float* bb = (const float*)&x2;
        float* lf = (float*)&lo;
        float* hf = (float*)&hi;
        #pragma unroll
        for (int j = 0; j < 4; j++) {
            float s, c;
            sincosf(fp * sfreq[i0 + j], &s, &c);
            lf[j] = a[j] * c - bb[j] * s;
            hf[j] = a[j] * s + bb[j] * c;
        }

        float4* orow = out + out_row_base(b, p, 0, maxkv) + h * VEC_PER_ROW;
        __stcs(&orow[d4],      lo);
        __stcs(&orow[d4 + 16], hi);
    } else if (gid < nAV) {
        // ---- value gather, p < BUDGET ----
        int j  = gid - nA;
        int d4 = (j & 15) * 2;             // pair of consecutive float4
        int h  = (j >> 4) & (HH - 1);
        int p  = (j >> 7) & (BUDGET - 1);
        int b  = j >> 19;

        int ctx = *ctxp;
        int ql  = __ldg(&qlens[b]);
        const float4* row = resolve_row(cache, vnew, b, p, 1, ctx, ql, maxkv, seq_len)
                            + h * VEC_PER_ROW;
        float4 v0 = __ldg(&row[d4]);
        float4 v1 = __ldg(&row[d4 + 1]);
        float4* orow = out + out_row_base(b, p, 1, maxkv) + h * VEC_PER_ROW;
        __stcs(&orow[d4],     v0);
        __stcs(&orow[d4 + 1], v1);
    } else {
        // ---- identity region: per batch, pages [BUDGET/16, maxkv/16) ----
        int j = gid - nAV;
        int b = j >> id_shift;
        long long off = (long long)(j & id_mask);   // f4-pair offset in chunk
        long long base = ((long long)b * (maxkv / PAGE) + (BUDGET / PAGE))
                         * F4_PER_PAGE;
        long long idx = base + off * 2;
        float4 v0 = __ldg(&cache[idx]);
        float4 v1 = __ldg(&cache[idx + 1]);
        __stcs(&out[idx],     v0);
        __stcs(&out[idx + 1], v1);
    }
}

extern "C" void kernel_launch(void* const* d_in, const int* in_sizes, int n_in,
                              void* d_out, int out_size) {
    const float4* cache = (const float4*)d_in[0];
    const float4* knew  = (const float4*)d_in[1];
    const float4* vnew  = (const float4*)d_in[2];
    const int*    qlens = (const int*)d_in[3];
    const int*    ctxp  = (const int*)d_in[5];   // context_len scalar (device)

    int bsz = in_sizes[3];
    int total_pos = in_sizes[0] / (2 * HH * DD);
    int maxkv = total_pos / bsz;                 // 8192
    int seq_len = in_sizes[1] / (bsz * HH * DD); // 2048

    // Region sizes (threads)
    int nA  = bsz * BUDGET * HH * (VEC_PER_ROW / 2);   // rope pairs
    int nV  = bsz * BUDGET * HH * (VEC_PER_ROW / 2);   // value 32B units
    int nAV = nA + nV;

    int id_pages = maxkv / PAGE - BUDGET / PAGE;                 // per batch
    long long id_pairs = (long long)id_pages * F4_PER_PAGE / 2;  // per batch (pow2)
    int id_shift = 0;
    while ((1LL << id_shift) < id_pairs) id_shift++;
    int id_mask = (int)(id_pairs - 1);

    int ntot = nAV + (int)(id_pairs * bsz);
    int blocks = (ntot + 255) / 256;

    skv_fused<<<blocks, 256>>>(cache, knew, vnew, qlens, ctxp,
                               (float4*)d_out, maxkv, seq_len,
                               nA, nAV, id_shift, id_mask, ntot);
}